// round 15
// baseline (speedup 1.0000x reference)
#include <cuda_runtime.h>
#include <cstdint>

// out[m][d] = sum_k x[m][k] * W[k][d];  M=8192, K=4096, N=32, fp32.
//
// R14: single-pass TF32 GEMM on mma.sync.m16n8k8 (baseline PTX; tcgen05
// rejected by harness sm_103 target). Replaces bf16x3 (3 products + 48
// split-instr/step) with 1 product: ~28 instr/step, tensor work -67%.
// Error model (validated on bf16x3: pred 1e-5, meas 4.8e-6): tf32 u=2^-11,
// norm rel_err ~ 4e-4 < 1e-3 gate, deterministic fixed-seed inputs.
// Skeleton = R10 (39.2us best): KSPLIT=8 -> 512 CTAs single wave, 8 warps,
// 32KB W table rebuilt mid-loop, fused deterministic last-CTA reduction.

#define M_TOTAL 8192
#define K_TOTAL 4096
#define N_OUT   32
#define KSPLIT  8
#define KPER    (K_TOTAL / KSPLIT)     // 512
#define KHALFC  256                    // k per table build
#define NITH    (KHALFC / 16)          // 16 steps per half
#define WARPS_CTA 8
#define THREADS  (WARPS_CTA * 32)      // 256
#define MB_ROWS  128
#define NMB      (M_TOTAL / MB_ROWS)   // 64
#define NCTA     (NMB * KSPLIT)        // 512
#define NBENT    (NITH * 4 * 4 * 8)    // 2048 entries (uint4) = 32 KB

__device__ float g_part[(size_t)KSPLIT * M_TOTAL * N_OUT];  // 8 MB (L2)
__device__ int   g_cnt[NMB];

__device__ __forceinline__ uint32_t to_tf32(float f) {
    uint32_t u;
    asm("cvt.rna.tf32.f32 %0, %1;" : "=r"(u) : "f"(f));
    return u;
}

// mma m16n8k8 tf32: A 4 regs, B 2 regs, D/C 4 fp32.
__device__ __forceinline__ void mma16808(float* d, uint32_t a0, uint32_t a1,
                                         uint32_t a2, uint32_t a3,
                                         uint32_t b0, uint32_t b1) {
    asm volatile(
        "mma.sync.aligned.m16n8k8.row.col.f32.tf32.tf32.f32 "
        "{%0,%1,%2,%3}, {%4,%5,%6,%7}, {%8,%9}, {%0,%1,%2,%3};"
        : "+f"(d[0]), "+f"(d[1]), "+f"(d[2]), "+f"(d[3])
        : "r"(a0), "r"(a1), "r"(a2), "r"(a3), "r"(b0), "r"(b1));
}

// Table slot (st, c, q, r). k_global = base + st*16 + c*4 + q; word j holds
// tf32(W[k][j*8+r]). Swizzle r' = (r+2c)&7: each LDS.128 8-lane phase
// (2 r-values x 4 c-values) hits 8 distinct 16B offsets mod 128B.
__device__ __forceinline__ int uidx(int st, int c, int q, int r) {
    return ((st * 4 + c) * 4 + q) * 8 + ((r + 2 * c) & 7);
}

__global__ void __launch_bounds__(THREADS)
gemm_tf32_kernel(const float* __restrict__ x, const float* __restrict__ w,
                 float* __restrict__ out) {
    __shared__ __align__(16) uint4 sT[NBENT];     // 32 KB tf32 W table

    const int tid  = threadIdx.x;
    const int wid  = tid >> 5, lane = tid & 31;
    const int mb   = blockIdx.x & (NMB - 1);
    const int kp   = blockIdx.x >> 6;             // NMB = 64
    const int k0   = kp * KPER;
    const int m0   = mb * MB_ROWS + wid * 16;
    const int r    = lane >> 2;
    const int c    = lane & 3;

    float d[4][4];
    #pragma unroll
    for (int j = 0; j < 4; j++)
        #pragma unroll
        for (int q = 0; q < 4; q++) d[j][q] = 0.f;

    const int ubase = uidx(0, c, 0, r);   // st stride +128 entries, q stride +8

    #pragma unroll 1
    for (int half = 0; half < 2; half++) {
        const int kh = k0 + half * KHALFC;

        // ---- (re)build tf32 W table for this half (W is L2-hot) ----
        if (half) __syncthreads();        // everyone done reading old table
        #pragma unroll
        for (int e0 = 0; e0 < NBENT / THREADS; e0++) {
            const int e  = e0 * THREADS + tid;
            const int er = e & 7, eq = (e >> 3) & 3;
            const int ec = (e >> 5) & 3, es = e >> 7;
            const int k  = kh + es * 16 + ec * 4 + eq;
            uint32_t v[4];
            #pragma unroll
            for (int j = 0; j < 4; j++)
                v[j] = to_tf32(w[(size_t)k * N_OUT + j * 8 + er]);
            sT[uidx(es, ec, eq, er)] = make_uint4(v[0], v[1], v[2], v[3]);
        }
        __syncthreads();

        const float* xa = x + (size_t)m0 * K_TOTAL + kh;

        struct AF { float4 p0, p1; };     // rows r, r+8; k = c*4..c*4+3
        auto load_a = [&](int it, AF& a) {
            const int col = it * 16 + c * 4;
            a.p0 = *(const float4*)(xa + (size_t)r       * K_TOTAL + col);
            a.p1 = *(const float4*)(xa + (size_t)(r + 8) * K_TOTAL + col);
        };
        auto step = [&](const AF& a, int it) {
            // B: 4 conflict-free LDS.128 (q = 0..3)
            const int u = ubase + it * 128;
            const uint4 B0 = sT[u], B1 = sT[u + 8], B2 = sT[u + 16], B3 = sT[u + 24];
            // A: 8 cvt to tf32
            uint32_t t0[4], t1[4];
            t0[0] = to_tf32(a.p0.x); t0[1] = to_tf32(a.p0.y);
            t0[2] = to_tf32(a.p0.z); t0[3] = to_tf32(a.p0.w);
            t1[0] = to_tf32(a.p1.x); t1[1] = to_tf32(a.p1.y);
            t1[2] = to_tf32(a.p1.z); t1[3] = to_tf32(a.p1.w);
            // kg=0: k slots from q0/q1 ; kg=1: q2/q3
            const uint32_t* q0 = &B0.x; const uint32_t* q1 = &B1.x;
            const uint32_t* q2 = &B2.x; const uint32_t* q3 = &B3.x;
            #pragma unroll
            for (int j = 0; j < 4; j++) {
                mma16808(d[j], t0[0], t1[0], t0[1], t1[1], q0[j], q1[j]);
                mma16808(d[j], t0[2], t1[2], t0[3], t1[3], q2[j], q3[j]);
            }
        };

        AF a0, a1;
        load_a(0, a0);
        #pragma unroll 1
        for (int it = 0; it < NITH; it += 2) {
            const int n1 = (it + 1 < NITH) ? it + 1 : it;
            load_a(n1, a1);
            step(a0, it);
            const int n2 = (it + 2 < NITH) ? it + 2 : it;
            load_a(n2, a0);
            step(a1, n1);
        }
    }

    // ---- store partials: rows r / r+8, cols j*8 + 2c ----
    float* base = g_part + ((size_t)kp * M_TOTAL + m0) * N_OUT;
    #pragma unroll
    for (int j = 0; j < 4; j++) {
        const int col = j * 8 + c * 2;
        *(float2*)(base + (size_t)r       * N_OUT + col) =
            make_float2(d[j][0], d[j][1]);
        *(float2*)(base + (size_t)(r + 8) * N_OUT + col) =
            make_float2(d[j][2], d[j][3]);
    }

    // ---- deterministic fused reduction (last CTA per m-block) ----
    __shared__ int s_last;
    __threadfence();
    __syncthreads();
    if (tid == 0) {
        s_last = (atomicAdd(&g_cnt[mb], 1) == KSPLIT - 1);
        if (s_last) __threadfence();
    }
    __syncthreads();
    if (s_last) {
        const int nf4 = MB_ROWS * N_OUT / 4;              // 1024 float4
        const float4* sc = (const float4*)g_part;
        float4* dst = (float4*)out + (size_t)mb * nf4;
        #pragma unroll 1
        for (int q = tid; q < nf4; q += THREADS) {
            const size_t o = (size_t)mb * nf4 + q;
            float4 v[KSPLIT];
            #pragma unroll
            for (int p = 0; p < KSPLIT; p++)            // MLP 8
                v[p] = sc[(size_t)p * (M_TOTAL * N_OUT / 4) + o];
            float4 sv = v[0];
            #pragma unroll
            for (int p = 1; p < KSPLIT; p++) {          // fixed order
                sv.x += v[p].x; sv.y += v[p].y;
                sv.z += v[p].z; sv.w += v[p].w;
            }
            dst[q] = sv;
        }
        if (tid == 0) g_cnt[mb] = 0;   // reset for graph replay
    }
}

extern "C" void kernel_launch(void* const* d_in, const int* in_sizes, int n_in,
                              void* d_out, int out_size) {
    const float* x = (const float*)d_in[0];   // [8192, 4096]
    const float* w = (const float*)d_in[1];   // [4096, 32]
    float* out = (float*)d_out;               // [8192, 32]

    gemm_tf32_kernel<<<NCTA, THREADS>>>(x, w, out);
}